// round 15
// baseline (speedup 1.0000x reference)
#include <cuda_runtime.h>
#include <cuda_fp16.h>
#include <cstdint>

#define TOT (4*256*256*128)
static __device__ unsigned short g_xuh[TOT];          // fp16 upsampled x (pixel-major)
static __device__ uint32_t g_qkvh[(size_t)4*256*256*192]; // QKV fp16, packed col-pairs
static __device__ unsigned short g_oh[TOT];           // attention out O fp16 (orig coords)
static __device__ unsigned short g_yh[TOT];           // y = attn+residual, fp16 pixel-major
// conv input planes: [n][cib(4)][h(256)][w(128)][j32(32 u32 = ci-pairs)]
static __device__ uint32_t g_yhi[TOT/2];
static __device__ uint32_t g_t1hi[TOT/2];
static __device__ unsigned short g_wc1[36*256*64];    // fp16 weights
static __device__ unsigned short g_wc2[40*256*64];
static __device__ unsigned short g_wq[384*128];       // qkv_w fp16 [n][k]
static __device__ unsigned short g_wp[128*128];       // proj_w fp16 [n][k]
static __device__ float g_b1[256], g_b2[256], g_bq[384], g_bp[128];

// ---------------- helpers -------------------------------------------------------
__device__ __forceinline__ uint32_t smem_u32(const void* p) {
    uint32_t r;
    asm("{ .reg .u64 t; cvta.to.shared.u64 t, %1; cvt.u32.u64 %0, t; }" : "=r"(r) : "l"(p));
    return r;
}
__device__ __forceinline__ unsigned short h16(float x) {
    return __half_as_ushort(__float2half_rn(x));
}
__device__ __forceinline__ void cp16(void* dst_smem, const void* src) {
    unsigned d = (unsigned)__cvta_generic_to_shared(dst_smem);
    asm volatile("cp.async.cg.shared.global [%0], [%1], 16;" :: "r"(d), "l"(src));
}
__device__ __forceinline__ void cp16z(void* dst_smem, const void* src, bool valid) {
    unsigned d = (unsigned)__cvta_generic_to_shared(dst_smem);
    int sz = valid ? 16 : 0;
    asm volatile("cp.async.cg.shared.global [%0], [%1], 16, %2;"
                 :: "r"(d), "l"(src), "r"(sz));
}
__device__ __forceinline__ void cpa_commit() { asm volatile("cp.async.commit_group;"); }
template <int N> __device__ __forceinline__ void cpa_wait() {
    asm volatile("cp.async.wait_group %0;" :: "n"(N));
}
__device__ __forceinline__ void ldmx4(uint32_t* r, uint32_t a) {
    asm volatile("ldmatrix.sync.aligned.m8n8.x4.shared.b16 {%0,%1,%2,%3}, [%4];"
                 : "=r"(r[0]), "=r"(r[1]), "=r"(r[2]), "=r"(r[3]) : "r"(a));
}
__device__ __forceinline__ void ldmx2(uint32_t* r, uint32_t a) {
    asm volatile("ldmatrix.sync.aligned.m8n8.x2.shared.b16 {%0,%1}, [%2];"
                 : "=r"(r[0]), "=r"(r[1]) : "r"(a));
}
__device__ __forceinline__ void mmah(float* d, const uint32_t* a, const uint32_t* b) {
    asm volatile(
        "mma.sync.aligned.m16n8k16.row.col.f32.f16.f16.f32 "
        "{%0,%1,%2,%3}, {%4,%5,%6,%7}, {%8,%9}, {%0,%1,%2,%3};"
        : "+f"(d[0]), "+f"(d[1]), "+f"(d[2]), "+f"(d[3])
        : "r"(a[0]), "r"(a[1]), "r"(a[2]), "r"(a[3]), "r"(b[0]), "r"(b[1]));
}

// ---------------- K1: bilinear 2x upsample -> fp16 ------------------------------
__global__ void k_upsample(const float* __restrict__ xin) {
    int idx = blockIdx.x * 256 + threadIdx.x;
    int cc = idx & 127;
    int t  = idx >> 7;
    int ww = t & 255; t >>= 8;
    int hh = t & 255;
    int b  = t >> 8;
    float pw = ww * (127.0f / 255.0f);
    int wlo = (int)pw; float fw = pw - (float)wlo; int whi = min(wlo + 1, 127);
    float pc = cc * (63.0f / 127.0f);
    int clo = (int)pc; float fc = pc - (float)clo; int chi = min(clo + 1, 63);
    const float* base = xin + ((b * 256 + hh) * 128) * 64;
    float v00 = base[wlo * 64 + clo], v01 = base[wlo * 64 + chi];
    float v10 = base[whi * 64 + clo], v11 = base[whi * 64 + chi];
    float v = (1.f - fw) * ((1.f - fc) * v00 + fc * v01)
            +        fw  * ((1.f - fc) * v10 + fc * v11);
    g_xuh[idx] = h16(v);
}

// ---------------- weight prep ---------------------------------------------------
__global__ void k_cvt_wq(const float* __restrict__ qkv_w, const float* __restrict__ qkv_b) {
    int idx = blockIdx.x * 256 + threadIdx.x;
    if (idx >= 49152) return;
    int k = idx & 127, nn = idx >> 7;
    g_wq[nn * 128 + k] = h16(qkv_w[k * 384 + nn]);
    if (k == 0) g_bq[nn] = qkv_b[nn];
}
__global__ void k_cvt_wp(const float* __restrict__ proj_w, const float* __restrict__ proj_b) {
    int idx = blockIdx.x * 256 + threadIdx.x;
    if (idx >= 16384) return;
    int k = idx & 127, nn = idx >> 7;
    g_wp[nn * 128 + k] = h16(proj_w[k * 128 + nn]);
    if (k == 0) g_bp[nn] = proj_b[nn];
}
__global__ void k_cvt_w1(const float* __restrict__ cw, const float* __restrict__ cb,
                         const float* __restrict__ bg, const float* __restrict__ bb,
                         const float* __restrict__ bm, const float* __restrict__ bv) {
    int idx = blockIdx.x * 256 + threadIdx.x;
    if (idx >= 36 * 256 * 64) return;
    int ci = idx & 63;
    int t = idx >> 6;
    int co = t & 255;
    int c = t >> 8;
    int kh = c / 12, kw = (c >> 2) % 3, ci0 = (c & 3) << 6;
    float s = bg[co] * rsqrtf(bv[co] + 1e-5f);
    g_wc1[(c * 256 + co) * 64 + ci] = h16(cw[((co * 256 + ci0 + ci) * 3 + kh) * 3 + kw] * s);
    if (c == 0 && ci == 0) g_b1[co] = cb[co] * s + bb[co] - bm[co] * s;
}
__global__ void k_cvt_w2(const float* __restrict__ cw, const float* __restrict__ cb,
                         const float* __restrict__ bg, const float* __restrict__ bb,
                         const float* __restrict__ bm, const float* __restrict__ bv,
                         const float* __restrict__ iw, const float* __restrict__ ibi,
                         const float* __restrict__ ig, const float* __restrict__ ib2,
                         const float* __restrict__ im, const float* __restrict__ iv) {
    int idx = blockIdx.x * 256 + threadIdx.x;
    if (idx >= 40 * 256 * 64) return;
    int ci = idx & 63;
    int t = idx >> 6;
    int co = t & 255;
    int c = t >> 8;
    float wv;
    if (c < 36) {
        int kh = c / 12, kw = (c >> 2) % 3, ci0 = (c & 3) << 6;
        wv = cw[((co * 256 + ci0 + ci) * 3 + kh) * 3 + kw] * (bg[co] * rsqrtf(bv[co] + 1e-5f));
    } else {
        wv = iw[co * 256 + ((c - 36) << 6) + ci] * (ig[co] * rsqrtf(iv[co] + 1e-5f));
    }
    g_wc2[(c * 256 + co) * 64 + ci] = h16(wv);
    if (c == 0 && ci == 0) {
        float s  = bg[co] * rsqrtf(bv[co] + 1e-5f);
        float si = ig[co] * rsqrtf(iv[co] + 1e-5f);
        g_b2[co] = cb[co] * s + bb[co] - bm[co] * s + ibi[co] * si + ib2[co] - im[co] * si;
    }
}

// ---------------- K-QKV: [262144 x 128] @ [128 x 384] fp16 ----------------------
#define QKV_STG 40960
__global__ __launch_bounds__(512, 1) void k_qkv() {
    extern __shared__ __align__(16) char smem[];
    int tid = threadIdx.x;
    int blk = blockIdx.x;                    // 2048
    int n = blk >> 9, hs = (blk >> 1) & 255, wb = blk & 1;
    int w0 = wb * 128;
    int h2 = (hs + 3) & 255;
    int warp = tid >> 5, lane = tid & 31;
    int wm = warp >> 2, wn = warp & 3;
    int gid = lane >> 2, tig = lane & 3;

    float acc[2][12][4];
    #pragma unroll
    for (int mt = 0; mt < 2; mt++)
        #pragma unroll
        for (int nt = 0; nt < 12; nt++)
            #pragma unroll
            for (int q = 0; q < 4; q++) acc[mt][nt][q] = 0.f;

    auto load_stage = [&](char* dst, int g) {
        int kc0 = g * 32;
        for (int i = tid; i < 1536; i += 512) {
            int c4 = i & 3; int nr = i >> 2;
            cp16(dst + nr * 80 + c4 * 16, g_wq + nr * 128 + kc0 + c4 * 8);
        }
        for (int i = tid; i < 512; i += 512) {
            int c4 = i & 3; int pr = i >> 2;
            int w2 = (w0 + pr + 3) & 255;
            cp16(dst + 30720 + pr * 80 + c4 * 16,
                 g_xuh + (((size_t)n * 256 + h2) * 256 + w2) * 128 + kc0 + c4 * 8);
        }
    };

    load_stage(smem, 0);
    cpa_commit();
    for (int g = 0; g < 4; g++) {
        if (g + 1 < 4) {
            load_stage(smem + ((g + 1) & 1) * QKV_STG, g + 1);
            cpa_commit();
            cpa_wait<1>();
        } else cpa_wait<0>();
        __syncthreads();

        uint32_t sb = smem_u32(smem + (g & 1) * QKV_STG);
        uint32_t aB = sb + 30720;
        int arow = wm * 32 + (lane & 15);
        int acol = ((lane >> 4) & 1) * 16;
        int brow = wn * 96 + (lane & 7);
        int bcol = ((lane >> 3) & 1) * 16;

        #pragma unroll
        for (int kc = 0; kc < 2; kc++) {
            uint32_t ah[2][4];
            #pragma unroll
            for (int mt = 0; mt < 2; mt++) {
                ldmx4(ah[mt], aB + (uint32_t)(arow + mt * 16) * 80 + kc * 32 + acol);
            }
            #pragma unroll
            for (int nt = 0; nt < 12; nt++) {
                uint32_t bd = sb + (uint32_t)(brow + nt * 8) * 80 + kc * 32 + bcol;
                uint32_t bv[2];
                ldmx2(bv, bd);
                #pragma unroll
                for (int mt = 0; mt < 2; mt++) mmah(acc[mt][nt], ah[mt], bv);
            }
        }
        __syncthreads();
    }

    size_t pbase = ((size_t)n * 256 + hs) * 256 + w0;
    #pragma unroll
    for (int nt = 0; nt < 12; nt++) {
        int col = wn * 96 + nt * 8 + 2 * tig;
        float b0 = g_bq[col], b1 = g_bq[col + 1];
        float sc = (col < 128) ? 0.17677669529663687f : 1.f;
        #pragma unroll
        for (int mt = 0; mt < 2; mt++) {
            int r0 = wm * 32 + mt * 16 + gid;
            uint32_t p0 = (uint32_t)h16((acc[mt][nt][0] + b0) * sc)
                        | ((uint32_t)h16((acc[mt][nt][1] + b1) * sc) << 16);
            uint32_t p1 = (uint32_t)h16((acc[mt][nt][2] + b0) * sc)
                        | ((uint32_t)h16((acc[mt][nt][3] + b1) * sc) << 16);
            g_qkvh[(pbase + r0) * 192 + (col >> 1)] = p0;
            g_qkvh[(pbase + r0 + 8) * 192 + (col >> 1)] = p1;
        }
    }
}

// ---------------- attention core: 2 windows per 256-thread block ----------------
__global__ __launch_bounds__(256) void k_attn_core(const float* __restrict__ rpb) {
    __shared__ float QKV[2][16][384];
    __shared__ float P[2][4][16][16];
    __shared__ float O[2][16][128];
    int tid = threadIdx.x;
    int wloc = tid >> 7;                    // window within block
    int tid128 = tid & 127;
    int blk = blockIdx.x * 2 + wloc;        // 16384 windows total
    int n = blk >> 12, widx = blk & 4095, wh = widx >> 6, wc = widx & 63;

    for (int idx = tid128; idx < 3072; idx += 128) {
        int t = idx / 192, c = idx - t * 192;
        size_t ps = ((size_t)n * 256 + wh * 4 + (t >> 2)) * 256 + wc * 4 + (t & 3);
        uint32_t pk = g_qkvh[ps * 192 + c];
        __half2 hv = *(__half2*)&pk;
        QKV[wloc][t][2 * c]     = __half2float(__low2half(hv));
        QKV[wloc][t][2 * c + 1] = __half2float(__high2half(hv));
    }
    __syncthreads();

    int warp = (tid >> 5) & 3, lane = tid & 31;   // warp = head
    if (lane < 16) {
        int t = lane, h = warp;
        float q[32];
        #pragma unroll
        for (int d = 0; d < 32; d++) q[d] = QKV[wloc][t][h * 32 + d];
        int i1 = t >> 2, j1 = t & 3;
        int rh1 = wh * 4 + i1, rw1 = wc * 4 + j1;
        int l1 = ((rh1 < 252) ? 0 : ((rh1 < 253) ? 1 : 2)) * 3
               + ((rw1 < 252) ? 0 : ((rw1 < 253) ? 1 : 2));
        float s[16], mx = -1e30f;
        #pragma unroll
        for (int u = 0; u < 16; u++) {
            float dot = 0.f;
            #pragma unroll
            for (int d = 0; d < 32; d++) dot += q[d] * QKV[wloc][u][128 + h * 32 + d];
            int i2 = u >> 2, j2 = u & 3;
            dot += rpb[((i1 - i2 + 3) * 7 + (j1 - j2 + 3)) * 4 + h];
            int rh2 = wh * 4 + i2, rw2 = wc * 4 + j2;
            int l2 = ((rh2 < 252) ? 0 : ((rh2 < 253) ? 1 : 2)) * 3
                   + ((rw2 < 252) ? 0 : ((rw2 < 253) ? 1 : 2));
            if (l1 != l2) dot -= 100.f;
            s[u] = dot; mx = fmaxf(mx, dot);
        }
        float sum = 0.f;
        #pragma unroll
        for (int u = 0; u < 16; u++) { s[u] = __expf(s[u] - mx); sum += s[u]; }
        float inv = 1.f / sum;
        #pragma unroll
        for (int u = 0; u < 16; u++) P[wloc][h][t][u] = s[u] * inv;
    }
    __syncwarp();
    {
        int h = warp, d = lane;
        #pragma unroll
        for (int t = 0; t < 16; t++) {
            float acc = 0.f;
            #pragma unroll
            for (int u = 0; u < 16; u++) acc += P[wloc][h][t][u] * QKV[wloc][u][256 + h * 32 + d];
            O[wloc][t][h * 32 + d] = acc;
        }
    }
    __syncthreads();

    int t = tid128 >> 3, c0 = (tid128 & 7) * 16;
    int hs = wh * 4 + (t >> 2), ws = wc * 4 + (t & 3);
    int hh2 = (hs + 3) & 255, ww2 = (ws + 3) & 255;
    size_t po = (((size_t)n * 256 + hh2) * 256 + ww2) * 128;
    #pragma unroll
    for (int c = 0; c < 16; c++) g_oh[po + c0 + c] = h16(O[wloc][t][c0 + c]);
}

// ---------------- K-proj: GEMM + bias + fp16 residual -> fp16 y -----------------
__global__ __launch_bounds__(512, 1) void k_proj() {
    extern __shared__ __align__(16) char smem[];
    int tid = threadIdx.x;
    int blk = blockIdx.x;
    size_t p0 = (size_t)blk * 128;
    int warp = tid >> 5, lane = tid & 31;
    int wm = warp >> 2, wn = warp & 3;
    int gid = lane >> 2, tig = lane & 3;

    for (int i = tid; i < 2048; i += 512) {
        int c16 = i & 15; int nr = i >> 4;
        cp16(smem + nr * 272 + c16 * 16, g_wp + nr * 128 + c16 * 8);
    }
    for (int i = tid; i < 2048; i += 512) {
        int c16 = i & 15; int pr = i >> 4;
        cp16(smem + 34816 + pr * 272 + c16 * 16, g_oh + (p0 + pr) * 128 + c16 * 8);
    }
    cpa_commit();
    cpa_wait<0>();
    __syncthreads();

    float acc[2][4][4];
    #pragma unroll
    for (int mt = 0; mt < 2; mt++)
        #pragma unroll
        for (int nt = 0; nt < 4; nt++)
            #pragma unroll
            for (int q = 0; q < 4; q++) acc[mt][nt][q] = 0.f;

    uint32_t sb = smem_u32(smem);
    uint32_t aB = sb + 34816;
    int arow = wm * 32 + (lane & 15);
    int acol = ((lane >> 4) & 1) * 16;
    int brow = wn * 32 + (lane & 7);
    int bcol = ((lane >> 3) & 1) * 16;

    #pragma unroll
    for (int kc = 0; kc < 8; kc++) {
        uint32_t ah[2][4];
        #pragma unroll
        for (int mt = 0; mt < 2; mt++) {
            ldmx4(ah[mt], aB + (uint32_t)(arow + mt * 16) * 272 + kc * 32 + acol);
        }
        #pragma unroll
        for (int nt = 0; nt < 4; nt++) {
            uint32_t bd = sb + (uint32_t)(brow + nt * 8) * 272 + kc * 32 + bcol;
            uint32_t bv[2];
            ldmx2(bv, bd);
            #pragma unroll
            for (int mt = 0; mt < 2; mt++) mmah(acc[mt][nt], ah[mt], bv);
        }
    }

    #pragma unroll
    for (int nt = 0; nt < 4; nt++) {
        int coe = wn * 32 + nt * 8 + 2 * tig;
        float b0 = g_bp[coe], b1 = g_bp[coe + 1];
        #pragma unroll
        for (int mt = 0; mt < 2; mt++) {
            #pragma unroll
            for (int half = 0; half < 2; half++) {
                size_t p = p0 + wm * 32 + mt * 16 + gid + half * 8;
                uint32_t rp = *(const uint32_t*)&g_xuh[p * 128 + coe];
                __half2 rh = *(__half2*)&rp;
                float v0 = acc[mt][nt][half * 2 + 0] + b0 + __half2float(__low2half(rh));
                float v1 = acc[mt][nt][half * 2 + 1] + b1 + __half2float(__high2half(rh));
                ((uint32_t*)g_yh)[(p * 128 + coe) >> 1] =
                    (uint32_t)h16(v0) | ((uint32_t)h16(v1) << 16);
            }
        }
    }
}

// ---------------- K-cvt-y: repack fp16 y into conv planes -----------------------
__global__ __launch_bounds__(256) void k_cvt_y() {
    __shared__ unsigned short sh[8192];
    int blk = blockIdx.x;                 // 4096 = 4*4*256
    int h = blk & 255;
    int cib = (blk >> 8) & 3;
    int n = blk >> 10;
    int tid = threadIdx.x;

    for (int i = tid; i < 8192; i += 256) {
        int ch = i >> 7, w = i & 127;
        sh[ch * 128 + w] = g_yh[(((size_t)n * 256 + cib * 64 + ch) * 256 + h) * 128 + w];
    }
    __syncthreads();

    size_t base = (((size_t)(n * 4 + cib) * 256 + h) * 128) * 32;
    for (int o = tid; o < 4096; o += 256) {
        int w = o >> 5, j = o & 31;
        g_yhi[base + o] = (uint32_t)sh[(2 * j) * 128 + w]
                        | ((uint32_t)sh[(2 * j + 1) * 128 + w] << 16);
    }
}

// ---------------- conv: fp16, K-chunk 64 stages, N=128, 2 CTAs/SM ---------------
#define CSTG 36864
#define CA_OFF 18432
template <int SECOND>
__global__ __launch_bounds__(512, 2) void k_conv_tc(float* __restrict__ out) {
    extern __shared__ __align__(16) char smem[];
    const int G = SECOND ? 40 : 36;
    const unsigned short* Wc = SECOND ? g_wc2 : g_wc1;

    int tid = threadIdx.x;
    int blk = blockIdx.x;                 // 2048 = n(4) x h(256) x cob(2)
    int cob = blk & 1;
    int h = (blk >> 1) & 255;
    int n = blk >> 9;
    int warp = tid >> 5, lane = tid & 31;
    int wm = warp >> 2, wn = warp & 3;
    int gid = lane >> 2, tig = lane & 3;

    float acc[2][4][4];
    #pragma unroll
    for (int mt = 0; mt < 2; mt++)
        #pragma unroll
        for (int nt = 0; nt < 4; nt++)
            #pragma unroll
            for (int q = 0; q < 4; q++) acc[mt][nt][q] = 0.f;

    auto params = [&](int c, int& kh, int& kw, int& cib, const uint32_t*& sH) {
        if (!SECOND) { kh = c / 12; kw = (c >> 2) % 3; cib = c & 3; sH = g_yhi; }
        else if (c < 36) { kh = c / 12; kw = (c >> 2) % 3; cib = c & 3; sH = g_t1hi; }
        else { kh = 1; kw = 1; cib = c - 36; sH = g_yhi; }
    };
    auto load_stage = [&](char* dst, int c) {
        for (int i = tid; i < 1024; i += 512) {
            int c8 = i & 7; int row = i >> 3;
            cp16(dst + row * 144 + c8 * 16,
                 Wc + ((size_t)c * 256 + cob * 128 + row) * 64 + c8 * 8);
        }
        int kh, kw, cib; const uint32_t* sH;
        params(c, kh, kw, cib, sH);
        int hh = h + kh - 1;
        bool okh = (unsigned)hh < 256u;
        int hc = okh ? hh : 0;
        for (int i = tid; i < 1024; i += 512) {
            int c8 = i & 7; int px = i >> 3;
            int ww = px + kw - 1;
            bool ok = okh && ((unsigned)ww < 128u);
            const uint32_t* s2 = sH + ((((size_t)(n * 4 + cib) * 256 + hc) * 128
                                        + (ok ? ww : 0)) * 32 + c8 * 4);
            cp16z(dst + CA_OFF + px * 144 + c8 * 16, s2, ok);
        }
    };

    load_stage(smem, 0);
    cpa_commit();

    for (int g = 0; g < G; g++) {
        if (g + 1 < G) {
            load_stage(smem + ((g + 1) & 1) * CSTG, g + 1);
            cpa_commit();
            cpa_wait<1>();
        } else cpa_wait<0>();
        __syncthreads();

        uint32_t sb = smem_u32(smem + (g & 1) * CSTG);
        uint32_t aB = sb + CA_OFF;
        int arow = wm * 32 + (lane & 15);
        int acol = ((lane >> 4) & 1) * 16;
        int brow = wn * 32 + (lane & 7);
        int bcol = ((lane >> 3) & 1) * 16;

        #pragma unroll
        for (int kc = 0; kc < 4; kc++) {
            uint32_t ah[2][4];
            #pragma unroll
            for (int mt = 0; mt < 2; mt++) {
                ldmx4(ah[mt], aB + (uint32_t)(arow + mt * 16) * 144 + kc * 32 + acol);
            }
            #pragma unroll
            for (int nt = 0; nt < 4; nt++) {
                uint32_t bd = sb + (uint32_t)(brow + nt * 8) * 144 + kc * 32 + bcol;
                uint32_t bv[2];
                ldmx2(bv, bd);
                #pragma unroll
                for (int mt = 0; mt < 2; mt++) mmah(acc[mt][nt], ah[mt], bv);
            }
        }
        __syncthreads();
    }

    const float* bsrc = SECOND ? g_b2 : g_b1;
    #pragma unroll
    for (int nt = 0; nt < 4; nt++) {
        int coe = cob * 128 + wn * 32 + nt * 8 + 2 * tig;
        float b0 = bsrc[coe], b1 = bsrc[coe + 1];
        int j = coe >> 1;
        #pragma unroll
        for (int mt = 0; mt < 2; mt++) {
            int p0 = wm * 32 + mt * 16 + gid;
            float v00 = fmaxf(acc[mt][nt][0] + b0, 0.f);
            float v01 = fmaxf(acc[mt][nt][1] + b1, 0.f);
            float v10 = fmaxf(acc[mt][nt][2] + b0, 0.f);
            float v11 = fmaxf(acc[mt][nt][3] + b1, 0.f);
            if (SECOND) {
                size_t o0 = (((size_t)n * 256 + coe) * 256 + h) * 128;
                out[o0 + p0] = v00;
                out[o0 + p0 + 8] = v10;
                out[o0 + 32768 + p0] = v01;
                out[o0 + 32768 + p0 + 8] = v11;
            } else {
                size_t ob = (((size_t)(n * 4 + (j >> 5)) * 256 + h) * 128) * 32 + (j & 31);
                g_t1hi[ob + (size_t)p0 * 32] =
                    (uint32_t)h16(v00) | ((uint32_t)h16(v01) << 16);
                g_t1hi[ob + (size_t)(p0 + 8) * 32] =
                    (uint32_t)h16(v10) | ((uint32_t)h16(v11) << 16);
            }
        }
    }
}

// ---------------- launcher ------------------------------------------------------
extern "C" void kernel_launch(void* const* d_in, const int* in_sizes, int n_in,
                              void* d_out, int out_size) {
    const float* x      = (const float*)d_in[0];
    const float* qkv_w  = (const float*)d_in[1];
    const float* qkv_b  = (const float*)d_in[2];
    const float* proj_w = (const float*)d_in[3];
    const float* proj_b = (const float*)d_in[4];
    const float* rpb    = (const float*)d_in[5];
    const float* c1w = (const float*)d_in[6];
    const float* c1b = (const float*)d_in[7];
    const float* b1g = (const float*)d_in[8];
    const float* b1b = (const float*)d_in[9];
    const float* b1m = (const float*)d_in[10];
    const float* b1v = (const float*)d_in[11];
    const float* c2w = (const float*)d_in[12];
    const float* c2b = (const float*)d_in[13];
    const float* b2g = (const float*)d_in[14];
    const float* b2b = (const float*)d_in[15];
    const float* b2m = (const float*)d_in[16];
    const float* b2v = (const float*)d_in[17];
    const float* idw = (const float*)d_in[18];
    const float* idb = (const float*)d_in[19];
    const float* big = (const float*)d_in[20];
    const float* bib = (const float*)d_in[21];
    const float* bim = (const float*)d_in[22];
    const float* biv = (const float*)d_in[23];
    float* out = (float*)d_out;

    cudaFuncSetAttribute(k_qkv, cudaFuncAttributeMaxDynamicSharedMemorySize, 2 * QKV_STG);
    cudaFuncSetAttribute(k_proj, cudaFuncAttributeMaxDynamicSharedMemorySize, 69632);
    cudaFuncSetAttribute(k_conv_tc<0>, cudaFuncAttributeMaxDynamicSharedMemorySize, 2 * CSTG);
    cudaFuncSetAttribute(k_conv_tc<1>, cudaFuncAttributeMaxDynamicSharedMemorySize, 2 * CSTG);

    k_upsample<<<TOT / 256, 256>>>(x);
    k_cvt_wq<<<192, 256>>>(qkv_w, qkv_b);
    k_cvt_wp<<<64, 256>>>(proj_w, proj_b);
    k_cvt_w1<<<2304, 256>>>(c1w, c1b, b1g, b1b, b1m, b1v);
    k_cvt_w2<<<2560, 256>>>(c2w, c2b, b2g, b2b, b2m, b2v,
                            idw, idb, big, bib, bim, biv);
    k_qkv<<<2048, 512, 2 * QKV_STG>>>();
    k_attn_core<<<8192, 256>>>(rpb);
    k_proj<<<2048, 512, 69632>>>();
    k_cvt_y<<<4096, 256>>>();
    k_conv_tc<0><<<2048, 512, 2 * CSTG>>>(out);
    k_conv_tc<1><<<2048, 512, 2 * CSTG>>>(out);
}

// round 17
// speedup vs baseline: 1.0599x; 1.0599x over previous
#include <cuda_runtime.h>
#include <cuda_fp16.h>
#include <cstdint>

#define TOT (4*256*256*128)
static __device__ unsigned short g_xuh[TOT];          // fp16 upsampled x (pixel-major)
static __device__ uint32_t g_qkvh[(size_t)4*256*256*192]; // QKV fp16, packed col-pairs
static __device__ unsigned short g_oh[TOT];           // attention out O fp16 (orig coords)
static __device__ unsigned short g_yh[TOT];           // y = attn+residual, fp16 pixel-major
// conv input planes: [n][cib(4)][h(256)][w(128)][j32(32 u32 = ci-pairs)]
static __device__ uint32_t g_yhi[TOT/2];
static __device__ uint32_t g_t1hi[TOT/2];
static __device__ unsigned short g_wc1[36*256*64];    // fp16 weights
static __device__ unsigned short g_wc2[40*256*64];
static __device__ unsigned short g_wq[384*128];       // qkv_w fp16 [n][k]
static __device__ unsigned short g_wp[128*128];       // proj_w fp16 [n][k]
static __device__ float g_b1[256], g_b2[256], g_bq[384], g_bp[128];

// ---------------- helpers -------------------------------------------------------
__device__ __forceinline__ uint32_t smem_u32(const void* p) {
    uint32_t r;
    asm("{ .reg .u64 t; cvta.to.shared.u64 t, %1; cvt.u32.u64 %0, t; }" : "=r"(r) : "l"(p));
    return r;
}
__device__ __forceinline__ unsigned short h16(float x) {
    return __half_as_ushort(__float2half_rn(x));
}
__device__ __forceinline__ void cp16(void* dst_smem, const void* src) {
    unsigned d = (unsigned)__cvta_generic_to_shared(dst_smem);
    asm volatile("cp.async.cg.shared.global [%0], [%1], 16;" :: "r"(d), "l"(src));
}
__device__ __forceinline__ void cp16z(void* dst_smem, const void* src, bool valid) {
    unsigned d = (unsigned)__cvta_generic_to_shared(dst_smem);
    int sz = valid ? 16 : 0;
    asm volatile("cp.async.cg.shared.global [%0], [%1], 16, %2;"
                 :: "r"(d), "l"(src), "r"(sz));
}
__device__ __forceinline__ void cpa_commit() { asm volatile("cp.async.commit_group;"); }
template <int N> __device__ __forceinline__ void cpa_wait() {
    asm volatile("cp.async.wait_group %0;" :: "n"(N));
}
__device__ __forceinline__ void ldmx4(uint32_t* r, uint32_t a) {
    asm volatile("ldmatrix.sync.aligned.m8n8.x4.shared.b16 {%0,%1,%2,%3}, [%4];"
                 : "=r"(r[0]), "=r"(r[1]), "=r"(r[2]), "=r"(r[3]) : "r"(a));
}
__device__ __forceinline__ void ldmx2(uint32_t* r, uint32_t a) {
    asm volatile("ldmatrix.sync.aligned.m8n8.x2.shared.b16 {%0,%1}, [%2];"
                 : "=r"(r[0]), "=r"(r[1]) : "r"(a));
}
__device__ __forceinline__ void mmah(float* d, const uint32_t* a, const uint32_t* b) {
    asm volatile(
        "mma.sync.aligned.m16n8k16.row.col.f32.f16.f16.f32 "
        "{%0,%1,%2,%3}, {%4,%5,%6,%7}, {%8,%9}, {%0,%1,%2,%3};"
        : "+f"(d[0]), "+f"(d[1]), "+f"(d[2]), "+f"(d[3])
        : "r"(a[0]), "r"(a[1]), "r"(a[2]), "r"(a[3]), "r"(b[0]), "r"(b[1]));
}

// ---------------- K1: bilinear 2x upsample -> fp16 ------------------------------
__global__ void k_upsample(const float* __restrict__ xin) {
    int idx = blockIdx.x * 256 + threadIdx.x;
    int cc = idx & 127;
    int t  = idx >> 7;
    int ww = t & 255; t >>= 8;
    int hh = t & 255;
    int b  = t >> 8;
    float pw = ww * (127.0f / 255.0f);
    int wlo = (int)pw; float fw = pw - (float)wlo; int whi = min(wlo + 1, 127);
    float pc = cc * (63.0f / 127.0f);
    int clo = (int)pc; float fc = pc - (float)clo; int chi = min(clo + 1, 63);
    const float* base = xin + ((b * 256 + hh) * 128) * 64;
    float v00 = base[wlo * 64 + clo], v01 = base[wlo * 64 + chi];
    float v10 = base[whi * 64 + clo], v11 = base[whi * 64 + chi];
    float v = (1.f - fw) * ((1.f - fc) * v00 + fc * v01)
            +        fw  * ((1.f - fc) * v10 + fc * v11);
    g_xuh[idx] = h16(v);
}

// ---------------- weight prep ---------------------------------------------------
__global__ void k_cvt_wq(const float* __restrict__ qkv_w, const float* __restrict__ qkv_b) {
    int idx = blockIdx.x * 256 + threadIdx.x;
    if (idx >= 49152) return;
    int k = idx & 127, nn = idx >> 7;
    g_wq[nn * 128 + k] = h16(qkv_w[k * 384 + nn]);
    if (k == 0) g_bq[nn] = qkv_b[nn];
}
__global__ void k_cvt_wp(const float* __restrict__ proj_w, const float* __restrict__ proj_b) {
    int idx = blockIdx.x * 256 + threadIdx.x;
    if (idx >= 16384) return;
    int k = idx & 127, nn = idx >> 7;
    g_wp[nn * 128 + k] = h16(proj_w[k * 128 + nn]);
    if (k == 0) g_bp[nn] = proj_b[nn];
}
__global__ void k_cvt_w1(const float* __restrict__ cw, const float* __restrict__ cb,
                         const float* __restrict__ bg, const float* __restrict__ bb,
                         const float* __restrict__ bm, const float* __restrict__ bv) {
    int idx = blockIdx.x * 256 + threadIdx.x;
    if (idx >= 36 * 256 * 64) return;
    int ci = idx & 63;
    int t = idx >> 6;
    int co = t & 255;
    int c = t >> 8;
    int kh = c / 12, kw = (c >> 2) % 3, ci0 = (c & 3) << 6;
    float s = bg[co] * rsqrtf(bv[co] + 1e-5f);
    g_wc1[(c * 256 + co) * 64 + ci] = h16(cw[((co * 256 + ci0 + ci) * 3 + kh) * 3 + kw] * s);
    if (c == 0 && ci == 0) g_b1[co] = cb[co] * s + bb[co] - bm[co] * s;
}
__global__ void k_cvt_w2(const float* __restrict__ cw, const float* __restrict__ cb,
                         const float* __restrict__ bg, const float* __restrict__ bb,
                         const float* __restrict__ bm, const float* __restrict__ bv,
                         const float* __restrict__ iw, const float* __restrict__ ibi,
                         const float* __restrict__ ig, const float* __restrict__ ib2,
                         const float* __restrict__ im, const float* __restrict__ iv) {
    int idx = blockIdx.x * 256 + threadIdx.x;
    if (idx >= 40 * 256 * 64) return;
    int ci = idx & 63;
    int t = idx >> 6;
    int co = t & 255;
    int c = t >> 8;
    float wv;
    if (c < 36) {
        int kh = c / 12, kw = (c >> 2) % 3, ci0 = (c & 3) << 6;
        wv = cw[((co * 256 + ci0 + ci) * 3 + kh) * 3 + kw] * (bg[co] * rsqrtf(bv[co] + 1e-5f));
    } else {
        wv = iw[co * 256 + ((c - 36) << 6) + ci] * (ig[co] * rsqrtf(iv[co] + 1e-5f));
    }
    g_wc2[(c * 256 + co) * 64 + ci] = h16(wv);
    if (c == 0 && ci == 0) {
        float s  = bg[co] * rsqrtf(bv[co] + 1e-5f);
        float si = ig[co] * rsqrtf(iv[co] + 1e-5f);
        g_b2[co] = cb[co] * s + bb[co] - bm[co] * s + ibi[co] * si + ib2[co] - im[co] * si;
    }
}

// ---------------- K-QKV: [262144 x 128] @ [128 x 384] fp16 ----------------------
#define QKV_STG 40960
__global__ __launch_bounds__(512, 1) void k_qkv() {
    extern __shared__ __align__(16) char smem[];
    int tid = threadIdx.x;
    int blk = blockIdx.x;                    // 2048
    int n = blk >> 9, hs = (blk >> 1) & 255, wb = blk & 1;
    int w0 = wb * 128;
    int h2 = (hs + 3) & 255;
    int warp = tid >> 5, lane = tid & 31;
    int wm = warp >> 2, wn = warp & 3;
    int gid = lane >> 2, tig = lane & 3;

    float acc[2][12][4];
    #pragma unroll
    for (int mt = 0; mt < 2; mt++)
        #pragma unroll
        for (int nt = 0; nt < 12; nt++)
            #pragma unroll
            for (int q = 0; q < 4; q++) acc[mt][nt][q] = 0.f;

    auto load_stage = [&](char* dst, int g) {
        int kc0 = g * 32;
        for (int i = tid; i < 1536; i += 512) {
            int c4 = i & 3; int nr = i >> 2;
            cp16(dst + nr * 80 + c4 * 16, g_wq + nr * 128 + kc0 + c4 * 8);
        }
        for (int i = tid; i < 512; i += 512) {
            int c4 = i & 3; int pr = i >> 2;
            int w2 = (w0 + pr + 3) & 255;
            cp16(dst + 30720 + pr * 80 + c4 * 16,
                 g_xuh + (((size_t)n * 256 + h2) * 256 + w2) * 128 + kc0 + c4 * 8);
        }
    };

    load_stage(smem, 0);
    cpa_commit();
    for (int g = 0; g < 4; g++) {
        if (g + 1 < 4) {
            load_stage(smem + ((g + 1) & 1) * QKV_STG, g + 1);
            cpa_commit();
            cpa_wait<1>();
        } else cpa_wait<0>();
        __syncthreads();

        uint32_t sb = smem_u32(smem + (g & 1) * QKV_STG);
        uint32_t aB = sb + 30720;
        int arow = wm * 32 + (lane & 15);
        int acol = ((lane >> 4) & 1) * 16;
        int brow = wn * 96 + (lane & 7);
        int bcol = ((lane >> 3) & 1) * 16;

        #pragma unroll
        for (int kc = 0; kc < 2; kc++) {
            uint32_t ah[2][4];
            #pragma unroll
            for (int mt = 0; mt < 2; mt++) {
                ldmx4(ah[mt], aB + (uint32_t)(arow + mt * 16) * 80 + kc * 32 + acol);
            }
            #pragma unroll
            for (int nt = 0; nt < 12; nt++) {
                uint32_t bd = sb + (uint32_t)(brow + nt * 8) * 80 + kc * 32 + bcol;
                uint32_t bv[2];
                ldmx2(bv, bd);
                #pragma unroll
                for (int mt = 0; mt < 2; mt++) mmah(acc[mt][nt], ah[mt], bv);
            }
        }
        __syncthreads();
    }

    size_t pbase = ((size_t)n * 256 + hs) * 256 + w0;
    #pragma unroll
    for (int nt = 0; nt < 12; nt++) {
        int col = wn * 96 + nt * 8 + 2 * tig;
        float b0 = g_bq[col], b1 = g_bq[col + 1];
        float sc = (col < 128) ? 0.17677669529663687f : 1.f;
        #pragma unroll
        for (int mt = 0; mt < 2; mt++) {
            int r0 = wm * 32 + mt * 16 + gid;
            uint32_t p0 = (uint32_t)h16((acc[mt][nt][0] + b0) * sc)
                        | ((uint32_t)h16((acc[mt][nt][1] + b1) * sc) << 16);
            uint32_t p1 = (uint32_t)h16((acc[mt][nt][2] + b0) * sc)
                        | ((uint32_t)h16((acc[mt][nt][3] + b1) * sc) << 16);
            g_qkvh[(pbase + r0) * 192 + (col >> 1)] = p0;
            g_qkvh[(pbase + r0 + 8) * 192 + (col >> 1)] = p1;
        }
    }
}

// ---------------- attention core: scores/softmax/PV per window (128 thr) --------
__global__ __launch_bounds__(128) void k_attn_core(const float* __restrict__ rpb) {
    __shared__ float QKV[16][384];
    __shared__ float P[4][16][16];
    __shared__ float O[16][128];
    int tid = threadIdx.x, blk = blockIdx.x;
    int n = blk >> 12, widx = blk & 4095, wh = widx >> 6, wc = widx & 63;

    for (int idx = tid; idx < 3072; idx += 128) {
        int t = idx / 192, c = idx - t * 192;
        size_t ps = ((size_t)n * 256 + wh * 4 + (t >> 2)) * 256 + wc * 4 + (t & 3);
        uint32_t pk = g_qkvh[ps * 192 + c];
        __half2 hv = *(__half2*)&pk;
        QKV[t][2 * c]     = __half2float(__low2half(hv));
        QKV[t][2 * c + 1] = __half2float(__high2half(hv));
    }
    __syncthreads();

    int warp = tid >> 5, lane = tid & 31;
    if (lane < 16) {
        int t = lane, h = warp;
        float q[32];
        #pragma unroll
        for (int d = 0; d < 32; d++) q[d] = QKV[t][h * 32 + d];
        int i1 = t >> 2, j1 = t & 3;
        int rh1 = wh * 4 + i1, rw1 = wc * 4 + j1;
        int l1 = ((rh1 < 252) ? 0 : ((rh1 < 253) ? 1 : 2)) * 3
               + ((rw1 < 252) ? 0 : ((rw1 < 253) ? 1 : 2));
        float s[16], mx = -1e30f;
        #pragma unroll
        for (int u = 0; u < 16; u++) {
            float dot = 0.f;
            #pragma unroll
            for (int d = 0; d < 32; d++) dot += q[d] * QKV[u][128 + h * 32 + d];
            int i2 = u >> 2, j2 = u & 3;
            dot += rpb[((i1 - i2 + 3) * 7 + (j1 - j2 + 3)) * 4 + h];
            int rh2 = wh * 4 + i2, rw2 = wc * 4 + j2;
            int l2 = ((rh2 < 252) ? 0 : ((rh2 < 253) ? 1 : 2)) * 3
                   + ((rw2 < 252) ? 0 : ((rw2 < 253) ? 1 : 2));
            if (l1 != l2) dot -= 100.f;
            s[u] = dot; mx = fmaxf(mx, dot);
        }
        float sum = 0.f;
        #pragma unroll
        for (int u = 0; u < 16; u++) { s[u] = __expf(s[u] - mx); sum += s[u]; }
        float inv = 1.f / sum;
        #pragma unroll
        for (int u = 0; u < 16; u++) P[h][t][u] = s[u] * inv;
    }
    __syncwarp();
    {
        int h = warp, d = lane;
        #pragma unroll
        for (int t = 0; t < 16; t++) {
            float acc = 0.f;
            #pragma unroll
            for (int u = 0; u < 16; u++) acc += P[h][t][u] * QKV[u][256 + h * 32 + d];
            O[t][h * 32 + d] = acc;
        }
    }
    __syncthreads();

    int t = tid >> 3, c0 = (tid & 7) * 16;
    int hs = wh * 4 + (t >> 2), ws = wc * 4 + (t & 3);
    int hh2 = (hs + 3) & 255, ww2 = (ws + 3) & 255;
    size_t po = (((size_t)n * 256 + hh2) * 256 + ww2) * 128;
    #pragma unroll
    for (int c = 0; c < 16; c++) g_oh[po + c0 + c] = h16(O[t][c0 + c]);
}

// ---------------- K-proj: GEMM + bias + fp16 residual -> fp16 y -----------------
__global__ __launch_bounds__(512, 1) void k_proj() {
    extern __shared__ __align__(16) char smem[];
    int tid = threadIdx.x;
    int blk = blockIdx.x;
    size_t p0 = (size_t)blk * 128;
    int warp = tid >> 5, lane = tid & 31;
    int wm = warp >> 2, wn = warp & 3;
    int gid = lane >> 2, tig = lane & 3;

    for (int i = tid; i < 2048; i += 512) {
        int c16 = i & 15; int nr = i >> 4;
        cp16(smem + nr * 272 + c16 * 16, g_wp + nr * 128 + c16 * 8);
    }
    for (int i = tid; i < 2048; i += 512) {
        int c16 = i & 15; int pr = i >> 4;
        cp16(smem + 34816 + pr * 272 + c16 * 16, g_oh + (p0 + pr) * 128 + c16 * 8);
    }
    cpa_commit();
    cpa_wait<0>();
    __syncthreads();

    float acc[2][4][4];
    #pragma unroll
    for (int mt = 0; mt < 2; mt++)
        #pragma unroll
        for (int nt = 0; nt < 4; nt++)
            #pragma unroll
            for (int q = 0; q < 4; q++) acc[mt][nt][q] = 0.f;

    uint32_t sb = smem_u32(smem);
    uint32_t aB = sb + 34816;
    int arow = wm * 32 + (lane & 15);
    int acol = ((lane >> 4) & 1) * 16;
    int brow = wn * 32 + (lane & 7);
    int bcol = ((lane >> 3) & 1) * 16;

    #pragma unroll
    for (int kc = 0; kc < 8; kc++) {
        uint32_t ah[2][4];
        #pragma unroll
        for (int mt = 0; mt < 2; mt++) {
            ldmx4(ah[mt], aB + (uint32_t)(arow + mt * 16) * 272 + kc * 32 + acol);
        }
        #pragma unroll
        for (int nt = 0; nt < 4; nt++) {
            uint32_t bd = sb + (uint32_t)(brow + nt * 8) * 272 + kc * 32 + bcol;
            uint32_t bv[2];
            ldmx2(bv, bd);
            #pragma unroll
            for (int mt = 0; mt < 2; mt++) mmah(acc[mt][nt], ah[mt], bv);
        }
    }

    #pragma unroll
    for (int nt = 0; nt < 4; nt++) {
        int coe = wn * 32 + nt * 8 + 2 * tig;
        float b0 = g_bp[coe], b1 = g_bp[coe + 1];
        #pragma unroll
        for (int mt = 0; mt < 2; mt++) {
            #pragma unroll
            for (int half = 0; half < 2; half++) {
                size_t p = p0 + wm * 32 + mt * 16 + gid + half * 8;
                uint32_t rp = *(const uint32_t*)&g_xuh[p * 128 + coe];
                __half2 rh = *(__half2*)&rp;
                float v0 = acc[mt][nt][half * 2 + 0] + b0 + __half2float(__low2half(rh));
                float v1 = acc[mt][nt][half * 2 + 1] + b1 + __half2float(__high2half(rh));
                ((uint32_t*)g_yh)[(p * 128 + coe) >> 1] =
                    (uint32_t)h16(v0) | ((uint32_t)h16(v1) << 16);
            }
        }
    }
}

// ---------------- K-cvt-y: repack fp16 y into conv planes -----------------------
__global__ __launch_bounds__(256) void k_cvt_y() {
    __shared__ unsigned short sh[8192];
    int blk = blockIdx.x;                 // 4096 = 4*4*256
    int h = blk & 255;
    int cib = (blk >> 8) & 3;
    int n = blk >> 10;
    int tid = threadIdx.x;

    for (int i = tid; i < 8192; i += 256) {
        int ch = i >> 7, w = i & 127;
        sh[ch * 128 + w] = g_yh[(((size_t)n * 256 + cib * 64 + ch) * 256 + h) * 128 + w];
    }
    __syncthreads();

    size_t base = (((size_t)(n * 4 + cib) * 256 + h) * 128) * 32;
    for (int o = tid; o < 4096; o += 256) {
        int w = o >> 5, j = o & 31;
        g_yhi[base + o] = (uint32_t)sh[(2 * j) * 128 + w]
                        | ((uint32_t)sh[(2 * j + 1) * 128 + w] << 16);
    }
}

// ---------------- conv: fp16, K-chunk 64 stages, N=128, 2 CTAs/SM ---------------
#define CSTG 36864
#define CA_OFF 18432
template <int SECOND>
__global__ __launch_bounds__(512, 2) void k_conv_tc(float* __restrict__ out) {
    extern __shared__ __align__(16) char smem[];
    const int G = SECOND ? 40 : 36;
    const unsigned short* Wc = SECOND ? g_wc2 : g_wc1;

    int tid = threadIdx.x;
    int blk = blockIdx.x;                 // 2048 = n(4) x h(256) x cob(2)
    int cob = blk & 1;
    int h = (blk >> 1) & 255;
    int n = blk >> 9;
    int warp = tid >> 5, lane = tid & 31;
    int wm = warp >> 2, wn = warp & 3;
    int gid = lane >> 2, tig = lane & 3;

    float acc[2][4][4];
    #pragma unroll
    for (int mt = 0; mt < 2; mt++)
        #pragma unroll
        for (int nt = 0; nt < 4; nt++)
            #pragma unroll
            for (int q = 0; q < 4; q++) acc[mt][nt][q] = 0.f;

    auto params = [&](int c, int& kh, int& kw, int& cib, const uint32_t*& sH) {
        if (!SECOND) { kh = c / 12; kw = (c >> 2) % 3; cib = c & 3; sH = g_yhi; }
        else if (c < 36) { kh = c / 12; kw = (c >> 2) % 3; cib = c & 3; sH = g_t1hi; }
        else { kh = 1; kw = 1; cib = c - 36; sH = g_yhi; }
    };
    auto load_stage = [&](char* dst, int c) {
        for (int i = tid; i < 1024; i += 512) {
            int c8 = i & 7; int row = i >> 3;
            cp16(dst + row * 144 + c8 * 16,
                 Wc + ((size_t)c * 256 + cob * 128 + row) * 64 + c8 * 8);
        }
        int kh, kw, cib; const uint32_t* sH;
        params(c, kh, kw, cib, sH);
        int hh = h + kh - 1;
        bool okh = (unsigned)hh < 256u;
        int hc = okh ? hh : 0;
        for (int i = tid; i < 1024; i += 512) {
            int c8 = i & 7; int px = i >> 3;
            int ww = px + kw - 1;
            bool ok = okh && ((unsigned)ww < 128u);
            const uint32_t* s2 = sH + ((((size_t)(n * 4 + cib) * 256 + hc) * 128
                                        + (ok ? ww : 0)) * 32 + c8 * 4);
            cp16z(dst + CA_OFF + px * 144 + c8 * 16, s2, ok);
        }
    };

    load_stage(smem, 0);
    cpa_commit();

    for (int g = 0; g < G; g++) {
        if (g + 1 < G) {
            load_stage(smem + ((g + 1) & 1) * CSTG, g + 1);
            cpa_commit();
            cpa_wait<1>();
        } else cpa_wait<0>();
        __syncthreads();

        uint32_t sb = smem_u32(smem + (g & 1) * CSTG);
        uint32_t aB = sb + CA_OFF;
        int arow = wm * 32 + (lane & 15);
        int acol = ((lane >> 4) & 1) * 16;
        int brow = wn * 32 + (lane & 7);
        int bcol = ((lane >> 3) & 1) * 16;

        #pragma unroll
        for (int kc = 0; kc < 4; kc++) {
            uint32_t ah[2][4];
            #pragma unroll
            for (int mt = 0; mt < 2; mt++) {
                ldmx4(ah[mt], aB + (uint32_t)(arow + mt * 16) * 144 + kc * 32 + acol);
            }
            #pragma unroll
            for (int nt = 0; nt < 4; nt++) {
                uint32_t bd = sb + (uint32_t)(brow + nt * 8) * 144 + kc * 32 + bcol;
                uint32_t bv[2];
                ldmx2(bv, bd);
                #pragma unroll
                for (int mt = 0; mt < 2; mt++) mmah(acc[mt][nt], ah[mt], bv);
            }
        }
        __syncthreads();
    }

    const float* bsrc = SECOND ? g_b2 : g_b1;
    #pragma unroll
    for (int nt = 0; nt < 4; nt++) {
        int coe = cob * 128 + wn * 32 + nt * 8 + 2 * tig;
        float b0 = bsrc[coe], b1 = bsrc[coe + 1];
        int j = coe >> 1;
        #pragma unroll
        for (int mt = 0; mt < 2; mt++) {
            int p0 = wm * 32 + mt * 16 + gid;
            float v00 = fmaxf(acc[mt][nt][0] + b0, 0.f);
            float v01 = fmaxf(acc[mt][nt][1] + b1, 0.f);
            float v10 = fmaxf(acc[mt][nt][2] + b0, 0.f);
            float v11 = fmaxf(acc[mt][nt][3] + b1, 0.f);
            if (SECOND) {
                size_t o0 = (((size_t)n * 256 + coe) * 256 + h) * 128;
                out[o0 + p0] = v00;
                out[o0 + p0 + 8] = v10;
                out[o0 + 32768 + p0] = v01;
                out[o0 + 32768 + p0 + 8] = v11;
            } else {
                size_t ob = (((size_t)(n * 4 + (j >> 5)) * 256 + h) * 128) * 32 + (j & 31);
                g_t1hi[ob + (size_t)p0 * 32] =
                    (uint32_t)h16(v00) | ((uint32_t)h16(v01) << 16);
                g_t1hi[ob + (size_t)(p0 + 8) * 32] =
                    (uint32_t)h16(v10) | ((uint32_t)h16(v11) << 16);
            }
        }
    }
}

// ---------------- launcher ------------------------------------------------------
extern "C" void kernel_launch(void* const* d_in, const int* in_sizes, int n_in,
                              void* d_out, int out_size) {
    const float* x      = (const float*)d_in[0];
    const float* qkv_w  = (const float*)d_in[1];
    const float* qkv_b  = (const float*)d_in[2];
    const float* proj_w = (const float*)d_in[3];
    const float* proj_b = (const float*)d_in[4];
    const float* rpb    = (const float*)d_in[5];
    const float* c1w = (const float*)d_in[6];
    const float* c1b = (const float*)d_in[7];
    const float* b1g = (const float*)d_in[8];
    const float* b1b = (const float*)d_in[9];
    const float* b1m = (const float*)d_in[10];
    const float* b1v = (const float*)d_in[11];
    const float* c2w = (const float*)d_in[12];
    const float* c2b = (const float*)d_in[13];
    const float* b2g = (const float*)d_in[14];
    const float* b2b = (const float*)d_in[15];
    const float* b2m = (const float*)d_in[16];
    const float* b2v = (const float*)d_in[17];
    const float* idw = (const float*)d_in[18];
    const float* idb = (const float*)d_in[19];
    const float* big = (const float*)d_in[20];
    const float* bib = (const float*)d_in[21];
    const float* bim = (const float*)d_in[22];
    const float* biv = (const float*)d_in[23];
    float* out = (float*)d_out;

    cudaFuncSetAttribute(k_qkv, cudaFuncAttributeMaxDynamicSharedMemorySize, 2 * QKV_STG);
    cudaFuncSetAttribute(k_proj, cudaFuncAttributeMaxDynamicSharedMemorySize, 69632);
    cudaFuncSetAttribute(k_conv_tc<0>, cudaFuncAttributeMaxDynamicSharedMemorySize, 2 * CSTG);
    cudaFuncSetAttribute(k_conv_tc<1>, cudaFuncAttributeMaxDynamicSharedMemorySize, 2 * CSTG);

    k_upsample<<<TOT / 256, 256>>>(x);
    k_cvt_wq<<<192, 256>>>(qkv_w, qkv_b);
    k_cvt_wp<<<64, 256>>>(proj_w, proj_b);
    k_cvt_w1<<<2304, 256>>>(c1w, c1b, b1g, b1b, b1m, b1v);
    k_cvt_w2<<<2560, 256>>>(c2w, c2b, b2g, b2b, b2m, b2v,
                            idw, idb, big, bib, bim, biv);
    k_qkv<<<2048, 512, 2 * QKV_STG>>>();
    k_attn_core<<<16384, 128>>>(rpb);
    k_proj<<<2048, 512, 69632>>>();
    k_cvt_y<<<4096, 256>>>();
    k_conv_tc<0><<<2048, 512, 2 * CSTG>>>(out);
    k_conv_tc<1><<<2048, 512, 2 * CSTG>>>(out);
}